// round 1
// baseline (speedup 1.0000x reference)
#include <cuda_runtime.h>
#include <cstdint>

// Problem constants
#define BB 2
#define SS 2048
#define DD 1024
#define HH 16
#define DKK 64
#define MTOT (BB*SS)          // 4096

// Scratch (device globals: allocation-guard safe)
__device__ float g_qh[BB*HH*SS*DKK];   // [B,H,S,DK]
__device__ float g_kh[BB*HH*SS*DKK];
__device__ float g_vh[BB*HH*SS*DKK];
__device__ float g_ctx[BB*SS*DD];      // [B,S,D]

// ---------------------------------------------------------------------------
// GEMM: C = A[M,K] @ W[N,K]^T + bias[N]
// headsplit=1: write C[m,n] -> out[((b*H+h)*S+s)*DK+dk]  (m=b*S+s, n=h*DK+dk)
// headsplit=0: write row-major C[m*N + n]
// Tiles: BM=BN=64, BK=16, 256 threads, 4x4 per thread.
// ---------------------------------------------------------------------------
__global__ __launch_bounds__(256) void gemm_bias_kernel(
    const float* __restrict__ A, const float* __restrict__ W,
    const float* __restrict__ bias, float* __restrict__ C,
    int M, int N, int K, int headsplit)
{
    __shared__ float As[16][64];   // As[k][m]
    __shared__ float Ws[16][64];   // Ws[k][n]

    const int tid = threadIdx.x;
    const int tx  = tid & 15;      // 0..15 -> 4 output cols each
    const int ty  = tid >> 4;      // 0..15 -> 4 output rows each
    const int row0 = blockIdx.y * 64;
    const int col0 = blockIdx.x * 64;

    const int ml = tid >> 2;             // 0..63
    const int kq = (tid & 3) << 2;       // 0,4,8,12

    float acc[4][4];
    #pragma unroll
    for (int i = 0; i < 4; i++)
        #pragma unroll
        for (int j = 0; j < 4; j++) acc[i][j] = 0.f;

    for (int k0 = 0; k0 < K; k0 += 16) {
        float4 av = *(const float4*)(A + (size_t)(row0 + ml) * K + k0 + kq);
        float4 wv = *(const float4*)(W + (size_t)(col0 + ml) * K + k0 + kq);
        As[kq+0][ml] = av.x; As[kq+1][ml] = av.y;
        As[kq+2][ml] = av.z; As[kq+3][ml] = av.w;
        Ws[kq+0][ml] = wv.x; Ws[kq+1][ml] = wv.y;
        Ws[kq+2][ml] = wv.z; Ws[kq+3][ml] = wv.w;
        __syncthreads();

        #pragma unroll
        for (int k = 0; k < 16; k++) {
            float4 a = *(const float4*)&As[k][ty << 2];
            float4 b = *(const float4*)&Ws[k][tx << 2];
            float af[4] = {a.x, a.y, a.z, a.w};
            float bf[4] = {b.x, b.y, b.z, b.w};
            #pragma unroll
            for (int i = 0; i < 4; i++)
                #pragma unroll
                for (int j = 0; j < 4; j++)
                    acc[i][j] = fmaf(af[i], bf[j], acc[i][j]);
        }
        __syncthreads();
    }

    const int r0 = ty << 2, c0 = tx << 2;
    float bv[4];
    #pragma unroll
    for (int j = 0; j < 4; j++) bv[j] = bias[col0 + c0 + j];

    #pragma unroll
    for (int i = 0; i < 4; i++) {
        const int mg = row0 + r0 + i;
        #pragma unroll
        for (int j = 0; j < 4; j++) {
            const int n = col0 + c0 + j;
            const float val = acc[i][j] + bv[j];
            if (headsplit) {
                const int b = mg >> 11;       // /S
                const int s = mg & (SS - 1);
                const int h = n >> 6;         // /DK
                const int dk = n & (DKK - 1);
                g_qh[0]; // no-op (keeps compiler quiet about unused on some paths)
                C[(((size_t)b * HH + h) * SS + s) * DKK + dk] = val;
            } else {
                C[(size_t)mg * DD + n] = val;
            }
        }
    }
}

// ---------------------------------------------------------------------------
// Flash attention (causal), fp32.
// grid: (S/64, B*H), block 256. 64 query rows per block; K tiles of 64.
// smem: Qt[k][r], KP (Kt[k][c] then P[r][k]), Vs[k][c].  3 * 16KB = 48KB.
// ---------------------------------------------------------------------------
__global__ __launch_bounds__(256) void flash_attn_kernel(
    const float* __restrict__ Qh, const float* __restrict__ Kh,
    const float* __restrict__ Vh, float* __restrict__ ctx)
{
    __shared__ float Qt[64][64];   // Qt[k][r]
    __shared__ float KP[64][64];   // Kt[k][c]  -> reused as P[r][k]
    __shared__ float Vs[64][64];   // Vs[k][c]

    const int tid = threadIdx.x;
    const int tx = tid & 15, ty = tid >> 4;
    const int r0 = ty << 2, c0 = tx << 2;
    const int qt = blockIdx.x;
    const int bh = blockIdx.y;
    const int q0 = qt * 64;

    const float* Qb = Qh + (size_t)bh * SS * DKK;
    const float* Kb = Kh + (size_t)bh * SS * DKK;
    const float* Vb = Vh + (size_t)bh * SS * DKK;

    // Load Q tile transposed: Qt[k][r]
    #pragma unroll
    for (int it = 0; it < 4; it++) {
        const int idx = tid + it * 256;
        const int r = idx >> 4;
        const int cq = (idx & 15) << 2;
        float4 v = *(const float4*)(Qb + (size_t)(q0 + r) * DKK + cq);
        Qt[cq+0][r] = v.x; Qt[cq+1][r] = v.y;
        Qt[cq+2][r] = v.z; Qt[cq+3][r] = v.w;
    }

    float o[4][4];
    float mrow[4], lrow[4];
    #pragma unroll
    for (int i = 0; i < 4; i++) {
        mrow[i] = -1e30f; lrow[i] = 0.f;
        #pragma unroll
        for (int j = 0; j < 4; j++) o[i][j] = 0.f;
    }

    for (int kt = 0; kt <= qt; kt++) {
        __syncthreads();   // previous iteration's P / V reads complete

        // Load K (transposed) and V tiles
        const int kr0 = kt * 64;
        #pragma unroll
        for (int it = 0; it < 4; it++) {
            const int idx = tid + it * 256;
            const int r = idx >> 4;
            const int cq = (idx & 15) << 2;
            float4 kv = *(const float4*)(Kb + (size_t)(kr0 + r) * DKK + cq);
            KP[cq+0][r] = kv.x; KP[cq+1][r] = kv.y;
            KP[cq+2][r] = kv.z; KP[cq+3][r] = kv.w;
            float4 vv = *(const float4*)(Vb + (size_t)(kr0 + r) * DKK + cq);
            *(float4*)&Vs[r][cq] = vv;
        }
        __syncthreads();

        // Scores: s[i][j] = Q[r0+i] . K[c0+j]
        float s[4][4];
        #pragma unroll
        for (int i = 0; i < 4; i++)
            #pragma unroll
            for (int j = 0; j < 4; j++) s[i][j] = 0.f;

        #pragma unroll 8
        for (int k = 0; k < 64; k++) {
            float4 a = *(const float4*)&Qt[k][r0];
            float4 b = *(const float4*)&KP[k][c0];
            float af[4] = {a.x, a.y, a.z, a.w};
            float bf[4] = {b.x, b.y, b.z, b.w};
            #pragma unroll
            for (int i = 0; i < 4; i++)
                #pragma unroll
                for (int j = 0; j < 4; j++)
                    s[i][j] = fmaf(af[i], bf[j], s[i][j]);
        }

        // scale + causal mask (only diagonal tile needs masking)
        const float sc = 0.125f;   // 1/sqrt(64)
        if (kt == qt) {
            #pragma unroll
            for (int i = 0; i < 4; i++)
                #pragma unroll
                for (int j = 0; j < 4; j++)
                    s[i][j] = (c0 + j > r0 + i) ? -1e30f : s[i][j] * sc;
        } else {
            #pragma unroll
            for (int i = 0; i < 4; i++)
                #pragma unroll
                for (int j = 0; j < 4; j++) s[i][j] *= sc;
        }

        // Online softmax (row state replicated across the 16 lanes of a row group)
        #pragma unroll
        for (int i = 0; i < 4; i++) {
            float rmax = fmaxf(fmaxf(s[i][0], s[i][1]), fmaxf(s[i][2], s[i][3]));
            #pragma unroll
            for (int off = 8; off >= 1; off >>= 1)
                rmax = fmaxf(rmax, __shfl_xor_sync(0xffffffffu, rmax, off));
            const float m_new = fmaxf(mrow[i], rmax);
            const float alpha = __expf(mrow[i] - m_new);
            float rsum = 0.f;
            #pragma unroll
            for (int j = 0; j < 4; j++) {
                s[i][j] = __expf(s[i][j] - m_new);   // s becomes p
                rsum += s[i][j];
            }
            #pragma unroll
            for (int off = 8; off >= 1; off >>= 1)
                rsum += __shfl_xor_sync(0xffffffffu, rsum, off);
            lrow[i] = lrow[i] * alpha + rsum;
            mrow[i] = m_new;
            #pragma unroll
            for (int j = 0; j < 4; j++) o[i][j] *= alpha;
        }

        __syncthreads();   // all score reads of KP(K) done
        // Write P[r][k] into KP buffer
        float* Pb = &KP[0][0];
        #pragma unroll
        for (int i = 0; i < 4; i++)
            #pragma unroll
            for (int j = 0; j < 4; j++)
                Pb[(r0 + i) * 64 + c0 + j] = s[i][j];
        __syncthreads();

        // O += P @ V
        #pragma unroll 8
        for (int k = 0; k < 64; k++) {
            float pf[4];
            #pragma unroll
            for (int i = 0; i < 4; i++) pf[i] = Pb[(r0 + i) * 64 + k];
            float4 vv = *(const float4*)&Vs[k][c0];
            float vf[4] = {vv.x, vv.y, vv.z, vv.w};
            #pragma unroll
            for (int i = 0; i < 4; i++)
                #pragma unroll
                for (int j = 0; j < 4; j++)
                    o[i][j] = fmaf(pf[i], vf[j], o[i][j]);
        }
    }

    // Epilogue: ctx[b, q0+r, h*DK + c] = o / l
    const int b = bh >> 4;        // /H
    const int h = bh & (HH - 1);
    #pragma unroll
    for (int i = 0; i < 4; i++) {
        const float inv = 1.f / lrow[i];
        const size_t base = ((size_t)b * SS + (q0 + r0 + i)) * DD + h * DKK + c0;
        #pragma unroll
        for (int j = 0; j < 4; j++)
            ctx[base + j] = o[i][j] * inv;
    }
}

// ---------------------------------------------------------------------------
// Launch
// ---------------------------------------------------------------------------
extern "C" void kernel_launch(void* const* d_in, const int* in_sizes, int n_in,
                              void* d_out, int out_size)
{
    const float* q  = (const float*)d_in[0];
    const float* k  = (const float*)d_in[1];
    const float* v  = (const float*)d_in[2];
    // d_in[3] = mask (int32, exact causal tril) -- structure exploited directly
    const float* wq = (const float*)d_in[4];
    const float* bq = (const float*)d_in[5];
    const float* wk = (const float*)d_in[6];
    const float* bk = (const float*)d_in[7];
    const float* wv = (const float*)d_in[8];
    const float* bv = (const float*)d_in[9];
    const float* wo = (const float*)d_in[10];
    const float* bo = (const float*)d_in[11];
    float* out = (float*)d_out;

    float *qh, *kh, *vh, *ctx;
    cudaGetSymbolAddress((void**)&qh,  g_qh);
    cudaGetSymbolAddress((void**)&kh,  g_kh);
    cudaGetSymbolAddress((void**)&vh,  g_vh);
    cudaGetSymbolAddress((void**)&ctx, g_ctx);

    dim3 ggrid(DD / 64, MTOT / 64);   // (16, 64)
    dim3 gblk(256);

    gemm_bias_kernel<<<ggrid, gblk>>>(q, wq, bq, qh, MTOT, DD, DD, 1);
    gemm_bias_kernel<<<ggrid, gblk>>>(k, wk, bk, kh, MTOT, DD, DD, 1);
    gemm_bias_kernel<<<ggrid, gblk>>>(v, wv, bv, vh, MTOT, DD, DD, 1);

    dim3 fgrid(SS / 64, BB * HH);     // (32, 32)
    flash_attn_kernel<<<fgrid, gblk>>>(qh, kh, vh, ctx);

    gemm_bias_kernel<<<ggrid, gblk>>>(ctx, wo, bo, out, MTOT, DD, DD, 0);
}

// round 2
// speedup vs baseline: 2.3923x; 2.3923x over previous
#include <cuda_runtime.h>
#include <cstdint>

// Problem constants
#define SS 2048
#define DD 1024
#define HH 16
#define DKK 64
#define MTOT 4096   // B*S

// Scratch (device globals: allocation-guard safe)
__device__ float g_qh[2*HH*SS*DKK];   // [B,H,S,DK]
__device__ float g_kh[2*HH*SS*DKK];
__device__ float g_vh[2*HH*SS*DKK];
__device__ float g_ctx[2*SS*DD];      // [B,S,D]

// ---------------------------------------------------------------------------
// tf32 helpers
// ---------------------------------------------------------------------------
__device__ __forceinline__ uint32_t f2tf(float x) {
    uint32_t u;
    asm("cvt.rna.tf32.f32 %0, %1;" : "=r"(u) : "f"(x));
    return u;
}
__device__ __forceinline__ float f2tff(float x) {
    return __uint_as_float(f2tf(x));
}

// D += A*B, m16n8k8 tf32 (A row-major, B col-major)
__device__ __forceinline__ void mma8(float* d, const uint32_t* a, uint32_t b0, uint32_t b1) {
    asm volatile(
        "mma.sync.aligned.m16n8k8.row.col.f32.tf32.tf32.f32 "
        "{%0,%1,%2,%3}, {%4,%5,%6,%7}, {%8,%9}, {%0,%1,%2,%3};\n"
        : "+f"(d[0]), "+f"(d[1]), "+f"(d[2]), "+f"(d[3])
        : "r"(a[0]), "r"(a[1]), "r"(a[2]), "r"(a[3]), "r"(b0), "r"(b1));
}

// ---------------------------------------------------------------------------
// GEMM: C = A[M=4096,K=1024] @ W[N=1024,K=1024]^T + bias
// Block 128x128, BK=16, 8 warps (warp tile 32x64).
// smem layout: (k, k+4) float2 pairs, row stride 18 float2 (36 words == 4 mod 32)
// headsplit=1: scatter into [B,H,S,DK]; else row-major [M,N].
// ---------------------------------------------------------------------------
__global__ __launch_bounds__(256) void gemm_tf32(
    const float* __restrict__ A, const float* __restrict__ W,
    const float* __restrict__ bias, float* __restrict__ C, int headsplit)
{
    __shared__ float2 As2[128][18];
    __shared__ float2 Ws2[128][18];

    const int tid = threadIdx.x;
    const int lane = tid & 31, wid = tid >> 5;
    const int warp_m = wid >> 1, warp_n = wid & 1;
    const int gq = lane >> 2, tq = lane & 3;
    const int row0 = blockIdx.y * 128, col0 = blockIdx.x * 128;

    const int lr = tid >> 1;          // 0..127 (tile row)
    const int kkst = tid & 1;         // which 8-wide k group
    const float* Ap = A + (size_t)(row0 + lr) * DD + kkst * 8;
    const float* Wp = W + (size_t)(col0 + lr) * DD + kkst * 8;

    float acc[2][8][4];
    #pragma unroll
    for (int im = 0; im < 2; im++)
        #pragma unroll
        for (int in_ = 0; in_ < 8; in_++)
            #pragma unroll
            for (int e = 0; e < 4; e++) acc[im][in_][e] = 0.f;

    // preload tile 0
    {
        float4 a0 = *(const float4*)(Ap);
        float4 a1 = *(const float4*)(Ap + 4);
        float4 w0 = *(const float4*)(Wp);
        float4 w1 = *(const float4*)(Wp + 4);
        As2[lr][kkst*4+0] = make_float2(f2tff(a0.x), f2tff(a1.x));
        As2[lr][kkst*4+1] = make_float2(f2tff(a0.y), f2tff(a1.y));
        As2[lr][kkst*4+2] = make_float2(f2tff(a0.z), f2tff(a1.z));
        As2[lr][kkst*4+3] = make_float2(f2tff(a0.w), f2tff(a1.w));
        Ws2[lr][kkst*4+0] = make_float2(f2tff(w0.x), f2tff(w1.x));
        Ws2[lr][kkst*4+1] = make_float2(f2tff(w0.y), f2tff(w1.y));
        Ws2[lr][kkst*4+2] = make_float2(f2tff(w0.z), f2tff(w1.z));
        Ws2[lr][kkst*4+3] = make_float2(f2tff(w0.w), f2tff(w1.w));
    }
    __syncthreads();

    const int NKB = DD / 16;   // 64
    for (int kb = 0; kb < NKB; kb++) {
        float4 na0, na1, nw0, nw1;
        if (kb < NKB - 1) {
            const float* ap = Ap + (kb + 1) * 16;
            const float* wp = Wp + (kb + 1) * 16;
            na0 = *(const float4*)(ap);
            na1 = *(const float4*)(ap + 4);
            nw0 = *(const float4*)(wp);
            nw1 = *(const float4*)(wp + 4);
        }

        #pragma unroll
        for (int kk = 0; kk < 2; kk++) {
            uint32_t af[2][4];
            #pragma unroll
            for (int im = 0; im < 2; im++) {
                const int r = warp_m * 32 + im * 16 + gq;
                float2 p0 = As2[r][kk*4 + tq];
                float2 p1 = As2[r + 8][kk*4 + tq];
                af[im][0] = __float_as_uint(p0.x);
                af[im][1] = __float_as_uint(p1.x);
                af[im][2] = __float_as_uint(p0.y);
                af[im][3] = __float_as_uint(p1.y);
            }
            #pragma unroll
            for (int in_ = 0; in_ < 8; in_++) {
                const int c = warp_n * 64 + in_ * 8 + gq;
                float2 pb = Ws2[c][kk*4 + tq];
                const uint32_t b0 = __float_as_uint(pb.x);
                const uint32_t b1 = __float_as_uint(pb.y);
                mma8(acc[0][in_], af[0], b0, b1);
                mma8(acc[1][in_], af[1], b0, b1);
            }
        }
        __syncthreads();
        if (kb < NKB - 1) {
            As2[lr][kkst*4+0] = make_float2(f2tff(na0.x), f2tff(na1.x));
            As2[lr][kkst*4+1] = make_float2(f2tff(na0.y), f2tff(na1.y));
            As2[lr][kkst*4+2] = make_float2(f2tff(na0.z), f2tff(na1.z));
            As2[lr][kkst*4+3] = make_float2(f2tff(na0.w), f2tff(na1.w));
            Ws2[lr][kkst*4+0] = make_float2(f2tff(nw0.x), f2tff(nw1.x));
            Ws2[lr][kkst*4+1] = make_float2(f2tff(nw0.y), f2tff(nw1.y));
            Ws2[lr][kkst*4+2] = make_float2(f2tff(nw0.z), f2tff(nw1.z));
            Ws2[lr][kkst*4+3] = make_float2(f2tff(nw0.w), f2tff(nw1.w));
            __syncthreads();
        }
    }

    // Epilogue with bias; known C fragment layout.
    #pragma unroll
    for (int im = 0; im < 2; im++) {
        const int mg0 = row0 + warp_m * 32 + im * 16 + gq;
        #pragma unroll
        for (int in_ = 0; in_ < 8; in_++) {
            const int c = col0 + warp_n * 64 + in_ * 8 + 2 * tq;
            const float b0 = bias[c], b1 = bias[c + 1];
            float2 v0 = make_float2(acc[im][in_][0] + b0, acc[im][in_][1] + b1);
            float2 v1 = make_float2(acc[im][in_][2] + b0, acc[im][in_][3] + b1);
            if (headsplit) {
                const int h = c >> 6, dk = c & 63;
                const int b_0 = mg0 >> 11, s_0 = mg0 & (SS - 1);
                const int mg1 = mg0 + 8;
                const int b_1 = mg1 >> 11, s_1 = mg1 & (SS - 1);
                *(float2*)&C[(((size_t)b_0 * HH + h) * SS + s_0) * DKK + dk] = v0;
                *(float2*)&C[(((size_t)b_1 * HH + h) * SS + s_1) * DKK + dk] = v1;
            } else {
                *(float2*)&C[(size_t)mg0 * DD + c] = v0;
                *(float2*)&C[(size_t)(mg0 + 8) * DD + c] = v1;
            }
        }
    }
}

// ---------------------------------------------------------------------------
// Flash attention (causal) on tensor cores, tf32.
// Block = 128 queries, 8 warps; each warp owns a 16-row strip (full 64-dk).
// K tiles of 64 keys. Online softmax in accumulator registers.
// ---------------------------------------------------------------------------
__global__ __launch_bounds__(256) void flash_tf32(
    const float* __restrict__ Qh, const float* __restrict__ Kh,
    const float* __restrict__ Vh, float* __restrict__ ctx)
{
    __shared__ float2 Ks2[64][34];     // (dk, dk+4) pairs per key row
    __shared__ float2 Vt2[64][34];     // transposed: (key, key+4) pairs per dk row
    __shared__ float  Ps[8][16][12];   // per-warp P-atom staging

    const int tid = threadIdx.x, lane = tid & 31, wid = tid >> 5;
    const int gq = lane >> 2, tq = lane & 3;
    const int q0 = blockIdx.x * 128, bh = blockIdx.y;
    const int strip = q0 + wid * 16;

    const float* Qb = Qh + (size_t)bh * SS * DKK;
    const float* Kb = Kh + (size_t)bh * SS * DKK;
    const float* Vb = Vh + (size_t)bh * SS * DKK;

    // Resident Q fragments (16 x 64), tf32
    uint32_t qf[8][4];
    #pragma unroll
    for (int ka = 0; ka < 8; ka++) {
        const float* qp = Qb + (size_t)(strip + gq) * DKK + ka * 8 + tq;
        qf[ka][0] = f2tf(qp[0]);
        qf[ka][1] = f2tf(qp[8 * DKK]);
        qf[ka][2] = f2tf(qp[4]);
        qf[ka][3] = f2tf(qp[8 * DKK + 4]);
    }

    float o[8][4];
    #pragma unroll
    for (int na = 0; na < 8; na++)
        #pragma unroll
        for (int e = 0; e < 4; e++) o[na][e] = 0.f;
    float m0 = -1e30f, m1 = -1e30f, l0 = 0.f, l1 = 0.f;

    const int ntiles = (q0 >> 6) + 2;
    for (int kt = 0; kt < ntiles; kt++) {
        __syncthreads();
        const int kr0 = kt * 64;
        // Cooperative K/V tile load + tf32 convert + pair-layout store
        #pragma unroll
        for (int i = 0; i < 4; i++) {
            const int idx = tid + i * 256;
            const int r = idx >> 4;            // key row 0..63
            const int c4 = (idx & 15) << 2;    // dk 0..60
            float4 kv = *(const float4*)(Kb + (size_t)(kr0 + r) * DKK + c4);
            float* krow = (float*)&Ks2[r][0];
            const int cb = ((c4 >> 3) << 3) + ((c4 >> 2) & 1);
            krow[cb + 0] = f2tff(kv.x);
            krow[cb + 2] = f2tff(kv.y);
            krow[cb + 4] = f2tff(kv.z);
            krow[cb + 6] = f2tff(kv.w);
            float4 vv = *(const float4*)(Vb + (size_t)(kr0 + r) * DKK + c4);
            float* vbase = (float*)&Vt2[0][0];
            const int vo = ((r >> 3) << 3) + ((r & 3) << 1) + ((r >> 2) & 1);
            vbase[(size_t)(c4 + 0) * 68 + vo] = f2tff(vv.x);
            vbase[(size_t)(c4 + 1) * 68 + vo] = f2tff(vv.y);
            vbase[(size_t)(c4 + 2) * 68 + vo] = f2tff(vv.z);
            vbase[(size_t)(c4 + 3) * 68 + vo] = f2tff(vv.w);
        }
        __syncthreads();

        if (kr0 <= strip + 15) {   // warp has >=1 unmasked key in this tile
            // S = Q K^T  (16 x 64)
            float s[8][4];
            #pragma unroll
            for (int na = 0; na < 8; na++) {
                #pragma unroll
                for (int e = 0; e < 4; e++) s[na][e] = 0.f;
            }
            #pragma unroll
            for (int na = 0; na < 8; na++) {
                #pragma unroll
                for (int ka = 0; ka < 8; ka++) {
                    float2 b = Ks2[na * 8 + gq][ka * 4 + tq];
                    mma8(s[na], qf[ka], __float_as_uint(b.x), __float_as_uint(b.y));
                }
            }
            // scale + causal mask
            const float sc = 0.125f;   // 1/sqrt(64)
            const int row0g = strip + gq, row1g = row0g + 8;
            if (kr0 + 63 > strip) {
                #pragma unroll
                for (int na = 0; na < 8; na++) {
                    const int c0g = kr0 + na * 8 + 2 * tq;
                    s[na][0] = (c0g     > row0g) ? -1e30f : s[na][0] * sc;
                    s[na][1] = (c0g + 1 > row0g) ? -1e30f : s[na][1] * sc;
                    s[na][2] = (c0g     > row1g) ? -1e30f : s[na][2] * sc;
                    s[na][3] = (c0g + 1 > row1g) ? -1e30f : s[na][3] * sc;
                }
            } else {
                #pragma unroll
                for (int na = 0; na < 8; na++) {
                    s[na][0] *= sc; s[na][1] *= sc; s[na][2] *= sc; s[na][3] *= sc;
                }
            }
            // online softmax (rows row0g, row1g owned by this quad)
            float mx0 = -1e30f, mx1 = -1e30f;
            #pragma unroll
            for (int na = 0; na < 8; na++) {
                mx0 = fmaxf(mx0, fmaxf(s[na][0], s[na][1]));
                mx1 = fmaxf(mx1, fmaxf(s[na][2], s[na][3]));
            }
            mx0 = fmaxf(mx0, __shfl_xor_sync(0xffffffffu, mx0, 1));
            mx0 = fmaxf(mx0, __shfl_xor_sync(0xffffffffu, mx0, 2));
            mx1 = fmaxf(mx1, __shfl_xor_sync(0xffffffffu, mx1, 1));
            mx1 = fmaxf(mx1, __shfl_xor_sync(0xffffffffu, mx1, 2));
            const float mn0 = fmaxf(m0, mx0), mn1 = fmaxf(m1, mx1);
            const float al0 = __expf(m0 - mn0), al1 = __expf(m1 - mn1);
            float sum0 = 0.f, sum1 = 0.f;
            #pragma unroll
            for (int na = 0; na < 8; na++) {
                s[na][0] = __expf(s[na][0] - mn0);
                s[na][1] = __expf(s[na][1] - mn0);
                s[na][2] = __expf(s[na][2] - mn1);
                s[na][3] = __expf(s[na][3] - mn1);
                sum0 += s[na][0] + s[na][1];
                sum1 += s[na][2] + s[na][3];
            }
            sum0 += __shfl_xor_sync(0xffffffffu, sum0, 1);
            sum0 += __shfl_xor_sync(0xffffffffu, sum0, 2);
            sum1 += __shfl_xor_sync(0xffffffffu, sum1, 1);
            sum1 += __shfl_xor_sync(0xffffffffu, sum1, 2);
            l0 = l0 * al0 + sum0;
            l1 = l1 * al1 + sum1;
            m0 = mn0; m1 = mn1;
            #pragma unroll
            for (int na = 0; na < 8; na++) {
                o[na][0] *= al0; o[na][1] *= al0;
                o[na][2] *= al1; o[na][3] *= al1;
            }
            // O += P V : stage each P k-atom through per-warp smem (C->A layout)
            #pragma unroll
            for (int kk = 0; kk < 8; kk++) {
                *(float2*)&Ps[wid][gq][2 * tq] =
                    make_float2(f2tff(s[kk][0]), f2tff(s[kk][1]));
                *(float2*)&Ps[wid][gq + 8][2 * tq] =
                    make_float2(f2tff(s[kk][2]), f2tff(s[kk][3]));
                __syncwarp();
                uint32_t pa[4];
                pa[0] = __float_as_uint(Ps[wid][gq][tq]);
                pa[1] = __float_as_uint(Ps[wid][gq + 8][tq]);
                pa[2] = __float_as_uint(Ps[wid][gq][tq + 4]);
                pa[3] = __float_as_uint(Ps[wid][gq + 8][tq + 4]);
                __syncwarp();
                #pragma unroll
                for (int na = 0; na < 8; na++) {
                    float2 b = Vt2[na * 8 + gq][kk * 4 + tq];
                    mma8(o[na], pa, __float_as_uint(b.x), __float_as_uint(b.y));
                }
            }
        }
    }

    // Epilogue: ctx[b, row, h*64 + col] = o / l
    const int bb = bh >> 4, h = bh & (HH - 1);
    const float inv0 = 1.f / l0, inv1 = 1.f / l1;
    const int row0g = strip + gq;
    #pragma unroll
    for (int na = 0; na < 8; na++) {
        const int c = h * DKK + na * 8 + 2 * tq;
        const size_t base0 = ((size_t)bb * SS + row0g) * DD + c;
        const size_t base1 = ((size_t)bb * SS + row0g + 8) * DD + c;
        *(float2*)&ctx[base0] = make_float2(o[na][0] * inv0, o[na][1] * inv0);
        *(float2*)&ctx[base1] = make_float2(o[na][2] * inv1, o[na][3] * inv1);
    }
}

// ---------------------------------------------------------------------------
// Launch
// ---------------------------------------------------------------------------
extern "C" void kernel_launch(void* const* d_in, const int* in_sizes, int n_in,
                              void* d_out, int out_size)
{
    const float* q  = (const float*)d_in[0];
    const float* k  = (const float*)d_in[1];
    const float* v  = (const float*)d_in[2];
    // d_in[3] = mask (exact causal tril) -- structure exploited directly
    const float* wq = (const float*)d_in[4];
    const float* bq = (const float*)d_in[5];
    const float* wk = (const float*)d_in[6];
    const float* bk = (const float*)d_in[7];
    const float* wv = (const float*)d_in[8];
    const float* bv = (const float*)d_in[9];
    const float* wo = (const float*)d_in[10];
    const float* bo = (const float*)d_in[11];
    float* out = (float*)d_out;

    float *qh, *kh, *vh, *ctx;
    cudaGetSymbolAddress((void**)&qh,  g_qh);
    cudaGetSymbolAddress((void**)&kh,  g_kh);
    cudaGetSymbolAddress((void**)&vh,  g_vh);
    cudaGetSymbolAddress((void**)&ctx, g_ctx);

    dim3 ggrid(DD / 128, MTOT / 128);   // (8, 32)
    dim3 blk(256);

    gemm_tf32<<<ggrid, blk>>>(q, wq, bq, qh, 1);
    gemm_tf32<<<ggrid, blk>>>(k, wk, bk, kh, 1);
    gemm_tf32<<<ggrid, blk>>>(v, wv, bv, vh, 1);

    dim3 fgrid(SS / 128, 2 * HH);       // (16, 32)
    flash_tf32<<<fgrid, blk>>>(qh, kh, vh, ctx);

    gemm_tf32<<<ggrid, blk>>>(ctx, wo, bo, out, 0);
}